// round 12
// baseline (speedup 1.0000x reference)
#include <cuda_runtime.h>
#include <cuda_bf16.h>
#include <cstdint>

#define N_NODES 100000
#define N_EDGES 1600000
#define IN_CH   128
#define HEADS   4
#define OUT_CH  32
#define HC      128
#define NEG_SLOPE 0.2f
#define EPS_F 1e-16f

#define NB_SCAN ((N_NODES + 255) / 256)   // 391 scan blocks

// ---------------- scratch (device globals; no allocation allowed) ----------
__device__ float g_xl[(size_t)N_NODES * HC];
__device__ float g_xr[(size_t)N_NODES * HC];
__device__ int   g_deg[N_NODES];
__device__ int   g_tmp[N_NODES];
__device__ int   g_cursor[N_NODES];     // rowstart before bucket; rowend after
__device__ int   g_part[NB_SCAN];
__device__ int   g_part2[NB_SCAN];
__device__ int   g_ssrc[N_EDGES];       // srcs bucketed by dst

__device__ __forceinline__ uint32_t to_tf32(float f) {
    uint32_t o;
    asm("cvt.rna.tf32.f32 %0, %1;" : "=r"(o) : "f"(f));
    return o;
}

// ---------------- K0: zero degree histogram ---------------------------------
__global__ void k_zero() {
    int i = blockIdx.x * 256 + threadIdx.x;
    if (i < N_NODES) g_deg[i] = 0;
}

// ---------------- K1: degree histogram --------------------------------------
__global__ __launch_bounds__(256) void k_degree(const int* __restrict__ ei) {
    int e = blockIdx.x * 256 + threadIdx.x;
    if (e < N_EDGES) atomicAdd(&g_deg[ei[N_EDGES + e]], 1);
}

// ---------------- K2a/b/c: two-level exclusive scan of degrees --------------
__global__ __launch_bounds__(256) void k_scan1() {
    __shared__ int s[256];
    int b = blockIdx.x, tid = threadIdx.x;
    int i = b * 256 + tid;
    int v = (i < N_NODES) ? g_deg[i] : 0;
    s[tid] = v;
    __syncthreads();
#pragma unroll
    for (int off = 1; off < 256; off <<= 1) {
        int t = (tid >= off) ? s[tid - off] : 0;
        __syncthreads();
        s[tid] += t;
        __syncthreads();
    }
    if (i < N_NODES) g_tmp[i] = s[tid];
    if (tid == 255) g_part[b] = s[255];
}
__global__ __launch_bounds__(512) void k_scan2() {
    __shared__ int s[512];
    int tid = threadIdx.x;
    int v = (tid < NB_SCAN) ? g_part[tid] : 0;
    s[tid] = v;
    __syncthreads();
#pragma unroll
    for (int off = 1; off < 512; off <<= 1) {
        int t = (tid >= off) ? s[tid - off] : 0;
        __syncthreads();
        s[tid] += t;
        __syncthreads();
    }
    if (tid < NB_SCAN) g_part2[tid] = s[tid] - v;   // exclusive
}
__global__ __launch_bounds__(256) void k_scan3() {
    int i = blockIdx.x * 256 + threadIdx.x;
    if (i >= N_NODES) return;
    g_cursor[i] = g_tmp[i] - g_deg[i] + g_part2[i >> 8];   // rowstart
}

// ---------------- K3: bucket edges by destination ----------------------------
__global__ __launch_bounds__(256) void k_bucket(const int* __restrict__ ei) {
    int e = blockIdx.x * 256 + threadIdx.x;
    if (e >= N_EDGES) return;
    int src = ei[e];
    int dst = ei[N_EDGES + e];
    int pos = atomicAdd(&g_cursor[dst], 1);
    g_ssrc[pos] = src;
}

// ---------------- K4: fused dual GEMM via tf32 tensor-core mma --------------
__global__ __launch_bounds__(256) void k_gemm(
    const float* __restrict__ X,
    const float* __restrict__ Wl,
    const float* __restrict__ Wr)
{
    __shared__ uint32_t xs[64][36];
    __shared__ uint32_t ws[32][264];

    const int tid  = threadIdx.x;
    const int warp = tid >> 5;
    const int lane = tid & 31;
    const int r     = warp & 3;
    const int cHalf = warp >> 2;
    const int row0 = blockIdx.x * 64;
    const int qr = lane >> 2;
    const int ql = lane & 3;

    float c[16][4];
#pragma unroll
    for (int j = 0; j < 16; j++)
#pragma unroll
        for (int q = 0; q < 4; q++) c[j][q] = 0.f;

    for (int chunk = 0; chunk < 4; chunk++) {
        const int k0 = chunk * 32;
        if (chunk) __syncthreads();
#pragma unroll
        for (int i = 0; i < 2; i++) {
            int li = tid + i * 256;
            int m  = li >> 3;
            int kq = (li & 7) * 4;
            float4 v = make_float4(0.f, 0.f, 0.f, 0.f);
            if (row0 + m < N_NODES)
                v = *(const float4*)&X[(size_t)(row0 + m) * IN_CH + k0 + kq];
            xs[m][kq + 0] = to_tf32(v.x); xs[m][kq + 1] = to_tf32(v.y);
            xs[m][kq + 2] = to_tf32(v.z); xs[m][kq + 3] = to_tf32(v.w);
        }
#pragma unroll
        for (int i = 0; i < 8; i++) {
            int li = tid + i * 256;
            int k  = li >> 6;
            int cq = (li & 63) * 4;
            const float* Wsrc = (cq < 128) ? Wl : Wr;
            int cc = (cq < 128) ? cq : (cq - 128);
            float4 v = *(const float4*)&Wsrc[(size_t)(k0 + k) * HC + cc];
            ws[k][cq + 0] = to_tf32(v.x); ws[k][cq + 1] = to_tf32(v.y);
            ws[k][cq + 2] = to_tf32(v.z); ws[k][cq + 3] = to_tf32(v.w);
        }
        __syncthreads();

#pragma unroll
        for (int ks = 0; ks < 4; ks++) {
            const int kk = ks * 8;
            uint32_t a0 = xs[r * 16 + qr    ][kk + ql    ];
            uint32_t a1 = xs[r * 16 + qr + 8][kk + ql    ];
            uint32_t a2 = xs[r * 16 + qr    ][kk + ql + 4];
            uint32_t a3 = xs[r * 16 + qr + 8][kk + ql + 4];
#pragma unroll
            for (int j = 0; j < 16; j++) {
                int nb = cHalf * 128 + j * 8 + qr;
                uint32_t b0 = ws[kk + ql    ][nb];
                uint32_t b1 = ws[kk + ql + 4][nb];
                asm volatile(
                    "mma.sync.aligned.m16n8k8.row.col.f32.tf32.tf32.f32 "
                    "{%0,%1,%2,%3}, {%4,%5,%6,%7}, {%8,%9}, {%0,%1,%2,%3};"
                    : "+f"(c[j][0]), "+f"(c[j][1]), "+f"(c[j][2]), "+f"(c[j][3])
                    : "r"(a0), "r"(a1), "r"(a2), "r"(a3), "r"(b0), "r"(b1));
            }
        }
    }

    float* Y = cHalf ? g_xr : g_xl;
    const int rbase = row0 + r * 16 + qr;
#pragma unroll
    for (int j = 0; j < 16; j++) {
        int col = j * 8 + 2 * ql;
        if (rbase < N_NODES)
            *(float2*)&Y[(size_t)rbase * HC + col] = make_float2(c[j][0], c[j][1]);
        if (rbase + 8 < N_NODES)
            *(float2*)&Y[(size_t)(rbase + 8) * HC + col] = make_float2(c[j][2], c[j][3]);
    }
}

// ---------------- K5: per-node aggregation, no max-shift --------------------
// t.lrelu(v) = (0.6t).v + (0.4t).|v| with t6/t4 precomputed per lane:
// per channel = FADD + 2 FFMA (|v| is free), 3 slots instead of 4.
#define LOGIT(p, a) { \
    float vx = a.x + xr4.x, vy = a.y + xr4.y; \
    float vz = a.z + xr4.z, vw = a.w + xr4.w; \
    p = t6.x * vx; \
    p = fmaf(t4.x, fabsf(vx), p); \
    p = fmaf(t6.y, vy, p); \
    p = fmaf(t4.y, fabsf(vy), p); \
    p = fmaf(t6.z, vz, p); \
    p = fmaf(t4.z, fabsf(vz), p); \
    p = fmaf(t6.w, vw, p); \
    p = fmaf(t4.w, fabsf(vw), p); \
    p += __shfl_xor_sync(0xffffffffu, p, 1); \
    p += __shfl_xor_sync(0xffffffffu, p, 2); \
    p += __shfl_xor_sync(0xffffffffu, p, 4); }

__global__ __launch_bounds__(256) void k_aggregate(
    const float* __restrict__ att,
    const float* __restrict__ bias,
    float* __restrict__ out)
{
    int node = blockIdx.x * 8 + (threadIdx.x >> 5);
    if (node >= N_NODES) return;
    int lane = threadIdx.x & 31;

    float4 xr4 = *(const float4*)&g_xr[(size_t)node * HC + lane * 4];
    float4 t   = *(const float4*)&att[lane * 4];
    float4 t6  = make_float4(0.6f * t.x, 0.6f * t.y, 0.6f * t.z, 0.6f * t.w);
    float4 t4  = make_float4(0.4f * t.x, 0.4f * t.y, 0.4f * t.z, 0.4f * t.w);

    float d = 0.f;
    float4 acc = make_float4(0.f, 0.f, 0.f, 0.f);

    int n     = g_deg[node];
    int start = g_cursor[node] - n;   // bucket left cursor at row end

    for (int base = 0; base < n; base += 32) {
        int cnt = min(32, n - base);
        int mysrc = (lane < cnt) ? g_ssrc[start + base + lane] : 0;
        int j = 0;
        for (; j + 4 <= cnt; j += 4) {
            int s0 = __shfl_sync(0xffffffffu, mysrc, j);
            int s1 = __shfl_sync(0xffffffffu, mysrc, j + 1);
            int s2 = __shfl_sync(0xffffffffu, mysrc, j + 2);
            int s3 = __shfl_sync(0xffffffffu, mysrc, j + 3);
            float4 a0 = *(const float4*)&g_xl[(size_t)s0 * HC + lane * 4];
            float4 a1 = *(const float4*)&g_xl[(size_t)s1 * HC + lane * 4];
            float4 a2 = *(const float4*)&g_xl[(size_t)s2 * HC + lane * 4];
            float4 a3 = *(const float4*)&g_xl[(size_t)s3 * HC + lane * 4];

            float p0, p1, p2, p3;
            LOGIT(p0, a0); LOGIT(p1, a1); LOGIT(p2, a2); LOGIT(p3, a3);

            float e0 = __expf(p0), e1 = __expf(p1);
            float e2 = __expf(p2), e3 = __expf(p3);
            d += (e0 + e1) + (e2 + e3);
            acc.x += fmaf(e0, a0.x, fmaf(e1, a1.x, fmaf(e2, a2.x, e3 * a3.x)));
            acc.y += fmaf(e0, a0.y, fmaf(e1, a1.y, fmaf(e2, a2.y, e3 * a3.y)));
            acc.z += fmaf(e0, a0.z, fmaf(e1, a1.z, fmaf(e2, a2.z, e3 * a3.z)));
            acc.w += fmaf(e0, a0.w, fmaf(e1, a1.w, fmaf(e2, a2.w, e3 * a3.w)));
        }
        for (; j < cnt; j++) {
            int s0 = __shfl_sync(0xffffffffu, mysrc, j);
            float4 a0 = *(const float4*)&g_xl[(size_t)s0 * HC + lane * 4];
            float p0;
            LOGIT(p0, a0);
            float ee = __expf(p0);
            d += ee;
            acc.x = fmaf(ee, a0.x, acc.x);
            acc.y = fmaf(ee, a0.y, acc.y);
            acc.z = fmaf(ee, a0.z, acc.z);
            acc.w = fmaf(ee, a0.w, acc.w);
        }
    }

    float inv = 1.f / (d + EPS_F);
    float4 b4 = *(const float4*)&bias[lane * 4];
    float4 o;
    o.x = fmaf(acc.x, inv, b4.x);
    o.y = fmaf(acc.y, inv, b4.y);
    o.z = fmaf(acc.z, inv, b4.z);
    o.w = fmaf(acc.w, inv, b4.w);
    __stcs((float4*)&out[(size_t)node * HC + lane * 4], o);
}

// ---------------- launch ----------------------------------------------------
extern "C" void kernel_launch(void* const* d_in, const int* in_sizes, int n_in,
                              void* d_out, int out_size)
{
    const float* x    = (const float*)d_in[0];
    const int*   ei   = (const int*)d_in[1];
    const float* Wl   = (const float*)d_in[2];
    const float* Wr   = (const float*)d_in[3];
    const float* att  = (const float*)d_in[4];
    const float* bias = (const float*)d_in[5];
    float* out = (float*)d_out;

    static cudaStream_t s_side = nullptr;
    static cudaEvent_t  ev_fork = nullptr, ev_join = nullptr;
    if (s_side == nullptr) {
        cudaStreamCreateWithFlags(&s_side, cudaStreamNonBlocking);
        cudaEventCreateWithFlags(&ev_fork, cudaEventDisableTiming);
        cudaEventCreateWithFlags(&ev_join, cudaEventDisableTiming);
    }

    // fork: GEMM on side stream (depends only on x, W)
    cudaEventRecord(ev_fork, (cudaStream_t)0);
    cudaStreamWaitEvent(s_side, ev_fork, 0);
    k_gemm<<<(N_NODES + 63) / 64, 256, 0, s_side>>>(x, Wl, Wr);
    cudaEventRecord(ev_join, s_side);

    // CSR build on main stream (depends only on edge_index)
    k_zero<<<NB_SCAN, 256>>>();
    k_degree<<<(N_EDGES + 255) / 256, 256>>>(ei);
    k_scan1<<<NB_SCAN, 256>>>();
    k_scan2<<<1, 512>>>();
    k_scan3<<<NB_SCAN, 256>>>();
    k_bucket<<<(N_EDGES + 255) / 256, 256>>>(ei);

    // join: aggregate needs both branches
    cudaStreamWaitEvent((cudaStream_t)0, ev_join, 0);
    k_aggregate<<<(N_NODES + 7) / 8, 256>>>(att, bias, out);
}

// round 13
// speedup vs baseline: 1.0459x; 1.0459x over previous
#include <cuda_runtime.h>
#include <cuda_bf16.h>
#include <cstdint>

#define N_NODES 100000
#define N_EDGES 1600000
#define IN_CH   128
#define HEADS   4
#define OUT_CH  32
#define HC      128
#define NEG_SLOPE 0.2f
#define EPS_F 1e-16f

#define NB_SCAN ((N_NODES + 255) / 256)   // 391 blocks over nodes

// ---------------- scratch (device globals; no allocation allowed) ----------
__device__ float g_xl[(size_t)N_NODES * HC];
__device__ float g_xr[(size_t)N_NODES * HC];
__device__ int   g_deg[N_NODES];        // zero-init at load; reset by k_aggregate
__device__ int   g_cursor[N_NODES];     // rowstart after alloc; rowend after bucket
__device__ int   g_total;               // row allocator; reset by k_degree
__device__ int   g_ssrc[N_EDGES];       // srcs bucketed by dst

__device__ __forceinline__ uint32_t to_tf32(float f) {
    uint32_t o;
    asm("cvt.rna.tf32.f32 %0, %1;" : "=r"(o) : "f"(f));
    return o;
}

// ---------------- K1: degree histogram (+ allocator reset) ------------------
__global__ __launch_bounds__(256) void k_degree(const int* __restrict__ ei) {
    int e = blockIdx.x * 256 + threadIdx.x;
    if (e == 0) g_total = 0;
    if (e < N_EDGES) atomicAdd(&g_deg[ei[N_EDGES + e]], 1);
}

// ---------------- K2: block-scan + atomic row allocation --------------------
// Row bases need not be in node order, only disjoint: block does a local
// scan and grabs a base range with one atomicAdd.
__global__ __launch_bounds__(256) void k_alloc() {
    __shared__ int s[256];
    __shared__ int base;
    int tid = threadIdx.x;
    int i = blockIdx.x * 256 + tid;
    int v = (i < N_NODES) ? g_deg[i] : 0;
    s[tid] = v;
    __syncthreads();
#pragma unroll
    for (int off = 1; off < 256; off <<= 1) {
        int t = (tid >= off) ? s[tid - off] : 0;
        __syncthreads();
        s[tid] += t;
        __syncthreads();
    }
    if (tid == 255) base = atomicAdd(&g_total, s[255]);
    __syncthreads();
    if (i < N_NODES) g_cursor[i] = base + s[tid] - v;   // exclusive rowstart
}

// ---------------- K3: bucket edges by destination ----------------------------
__global__ __launch_bounds__(256) void k_bucket(const int* __restrict__ ei) {
    int e = blockIdx.x * 256 + threadIdx.x;
    if (e >= N_EDGES) return;
    int src = ei[e];
    int dst = ei[N_EDGES + e];
    int pos = atomicAdd(&g_cursor[dst], 1);
    g_ssrc[pos] = src;
}

// ---------------- K4: fused dual GEMM via tf32 tensor-core mma --------------
__global__ __launch_bounds__(256) void k_gemm(
    const float* __restrict__ X,
    const float* __restrict__ Wl,
    const float* __restrict__ Wr)
{
    __shared__ uint32_t xs[64][36];
    __shared__ uint32_t ws[32][264];

    const int tid  = threadIdx.x;
    const int warp = tid >> 5;
    const int lane = tid & 31;
    const int r     = warp & 3;
    const int cHalf = warp >> 2;
    const int row0 = blockIdx.x * 64;
    const int qr = lane >> 2;
    const int ql = lane & 3;

    float c[16][4];
#pragma unroll
    for (int j = 0; j < 16; j++)
#pragma unroll
        for (int q = 0; q < 4; q++) c[j][q] = 0.f;

    for (int chunk = 0; chunk < 4; chunk++) {
        const int k0 = chunk * 32;
        if (chunk) __syncthreads();
#pragma unroll
        for (int i = 0; i < 2; i++) {
            int li = tid + i * 256;
            int m  = li >> 3;
            int kq = (li & 7) * 4;
            float4 v = make_float4(0.f, 0.f, 0.f, 0.f);
            if (row0 + m < N_NODES)
                v = *(const float4*)&X[(size_t)(row0 + m) * IN_CH + k0 + kq];
            xs[m][kq + 0] = to_tf32(v.x); xs[m][kq + 1] = to_tf32(v.y);
            xs[m][kq + 2] = to_tf32(v.z); xs[m][kq + 3] = to_tf32(v.w);
        }
#pragma unroll
        for (int i = 0; i < 8; i++) {
            int li = tid + i * 256;
            int k  = li >> 6;
            int cq = (li & 63) * 4;
            const float* Wsrc = (cq < 128) ? Wl : Wr;
            int cc = (cq < 128) ? cq : (cq - 128);
            float4 v = *(const float4*)&Wsrc[(size_t)(k0 + k) * HC + cc];
            ws[k][cq + 0] = to_tf32(v.x); ws[k][cq + 1] = to_tf32(v.y);
            ws[k][cq + 2] = to_tf32(v.z); ws[k][cq + 3] = to_tf32(v.w);
        }
        __syncthreads();

#pragma unroll
        for (int ks = 0; ks < 4; ks++) {
            const int kk = ks * 8;
            uint32_t a0 = xs[r * 16 + qr    ][kk + ql    ];
            uint32_t a1 = xs[r * 16 + qr + 8][kk + ql    ];
            uint32_t a2 = xs[r * 16 + qr    ][kk + ql + 4];
            uint32_t a3 = xs[r * 16 + qr + 8][kk + ql + 4];
#pragma unroll
            for (int j = 0; j < 16; j++) {
                int nb = cHalf * 128 + j * 8 + qr;
                uint32_t b0 = ws[kk + ql    ][nb];
                uint32_t b1 = ws[kk + ql + 4][nb];
                asm volatile(
                    "mma.sync.aligned.m16n8k8.row.col.f32.tf32.tf32.f32 "
                    "{%0,%1,%2,%3}, {%4,%5,%6,%7}, {%8,%9}, {%0,%1,%2,%3};"
                    : "+f"(c[j][0]), "+f"(c[j][1]), "+f"(c[j][2]), "+f"(c[j][3])
                    : "r"(a0), "r"(a1), "r"(a2), "r"(a3), "r"(b0), "r"(b1));
            }
        }
    }

    float* Y = cHalf ? g_xr : g_xl;
    const int rbase = row0 + r * 16 + qr;
#pragma unroll
    for (int j = 0; j < 16; j++) {
        int col = j * 8 + 2 * ql;
        if (rbase < N_NODES)
            *(float2*)&Y[(size_t)rbase * HC + col] = make_float2(c[j][0], c[j][1]);
        if (rbase + 8 < N_NODES)
            *(float2*)&Y[(size_t)(rbase + 8) * HC + col] = make_float2(c[j][2], c[j][3]);
    }
}

// ---------------- K5: per-node aggregation, no max-shift --------------------
#define LOGIT(p, a) { \
    float vx = a.x + xr4.x, vy = a.y + xr4.y; \
    float vz = a.z + xr4.z, vw = a.w + xr4.w; \
    p = t6.x * vx; \
    p = fmaf(t4.x, fabsf(vx), p); \
    p = fmaf(t6.y, vy, p); \
    p = fmaf(t4.y, fabsf(vy), p); \
    p = fmaf(t6.z, vz, p); \
    p = fmaf(t4.z, fabsf(vz), p); \
    p = fmaf(t6.w, vw, p); \
    p = fmaf(t4.w, fabsf(vw), p); \
    p += __shfl_xor_sync(0xffffffffu, p, 1); \
    p += __shfl_xor_sync(0xffffffffu, p, 2); \
    p += __shfl_xor_sync(0xffffffffu, p, 4); }

__global__ __launch_bounds__(256) void k_aggregate(
    const float* __restrict__ att,
    const float* __restrict__ bias,
    float* __restrict__ out)
{
    int node = blockIdx.x * 8 + (threadIdx.x >> 5);
    if (node >= N_NODES) return;
    int lane = threadIdx.x & 31;

    float4 xr4 = *(const float4*)&g_xr[(size_t)node * HC + lane * 4];
    float4 t   = *(const float4*)&att[lane * 4];
    float4 t6  = make_float4(0.6f * t.x, 0.6f * t.y, 0.6f * t.z, 0.6f * t.w);
    float4 t4  = make_float4(0.4f * t.x, 0.4f * t.y, 0.4f * t.z, 0.4f * t.w);

    float d = 0.f;
    float4 acc = make_float4(0.f, 0.f, 0.f, 0.f);

    int n     = g_deg[node];
    int start = g_cursor[node] - n;   // bucket left cursor at row end
    if (lane == 0) g_deg[node] = 0;   // reset histogram for next call

    for (int base = 0; base < n; base += 32) {
        int cnt = min(32, n - base);
        int mysrc = (lane < cnt) ? g_ssrc[start + base + lane] : 0;
        int j = 0;
        for (; j + 4 <= cnt; j += 4) {
            int s0 = __shfl_sync(0xffffffffu, mysrc, j);
            int s1 = __shfl_sync(0xffffffffu, mysrc, j + 1);
            int s2 = __shfl_sync(0xffffffffu, mysrc, j + 2);
            int s3 = __shfl_sync(0xffffffffu, mysrc, j + 3);
            float4 a0 = *(const float4*)&g_xl[(size_t)s0 * HC + lane * 4];
            float4 a1 = *(const float4*)&g_xl[(size_t)s1 * HC + lane * 4];
            float4 a2 = *(const float4*)&g_xl[(size_t)s2 * HC + lane * 4];
            float4 a3 = *(const float4*)&g_xl[(size_t)s3 * HC + lane * 4];

            float p0, p1, p2, p3;
            LOGIT(p0, a0); LOGIT(p1, a1); LOGIT(p2, a2); LOGIT(p3, a3);

            float e0 = __expf(p0), e1 = __expf(p1);
            float e2 = __expf(p2), e3 = __expf(p3);
            d += (e0 + e1) + (e2 + e3);
            acc.x += fmaf(e0, a0.x, fmaf(e1, a1.x, fmaf(e2, a2.x, e3 * a3.x)));
            acc.y += fmaf(e0, a0.y, fmaf(e1, a1.y, fmaf(e2, a2.y, e3 * a3.y)));
            acc.z += fmaf(e0, a0.z, fmaf(e1, a1.z, fmaf(e2, a2.z, e3 * a3.z)));
            acc.w += fmaf(e0, a0.w, fmaf(e1, a1.w, fmaf(e2, a2.w, e3 * a3.w)));
        }
        for (; j < cnt; j++) {
            int s0 = __shfl_sync(0xffffffffu, mysrc, j);
            float4 a0 = *(const float4*)&g_xl[(size_t)s0 * HC + lane * 4];
            float p0;
            LOGIT(p0, a0);
            float ee = __expf(p0);
            d += ee;
            acc.x = fmaf(ee, a0.x, acc.x);
            acc.y = fmaf(ee, a0.y, acc.y);
            acc.z = fmaf(ee, a0.z, acc.z);
            acc.w = fmaf(ee, a0.w, acc.w);
        }
    }

    float inv = 1.f / (d + EPS_F);
    float4 b4 = *(const float4*)&bias[lane * 4];
    float4 o;
    o.x = fmaf(acc.x, inv, b4.x);
    o.y = fmaf(acc.y, inv, b4.y);
    o.z = fmaf(acc.z, inv, b4.z);
    o.w = fmaf(acc.w, inv, b4.w);
    __stcs((float4*)&out[(size_t)node * HC + lane * 4], o);
}

// ---------------- launch ----------------------------------------------------
extern "C" void kernel_launch(void* const* d_in, const int* in_sizes, int n_in,
                              void* d_out, int out_size)
{
    const float* x    = (const float*)d_in[0];
    const int*   ei   = (const int*)d_in[1];
    const float* Wl   = (const float*)d_in[2];
    const float* Wr   = (const float*)d_in[3];
    const float* att  = (const float*)d_in[4];
    const float* bias = (const float*)d_in[5];
    float* out = (float*)d_out;

    static cudaStream_t s_side = nullptr;
    static cudaEvent_t  ev_fork = nullptr, ev_join = nullptr;
    if (s_side == nullptr) {
        cudaStreamCreateWithFlags(&s_side, cudaStreamNonBlocking);
        cudaEventCreateWithFlags(&ev_fork, cudaEventDisableTiming);
        cudaEventCreateWithFlags(&ev_join, cudaEventDisableTiming);
    }

    // fork: GEMM on side stream (depends only on x, W)
    cudaEventRecord(ev_fork, (cudaStream_t)0);
    cudaStreamWaitEvent(s_side, ev_fork, 0);
    k_gemm<<<(N_NODES + 63) / 64, 256, 0, s_side>>>(x, Wl, Wr);
    cudaEventRecord(ev_join, s_side);

    // CSR build on main stream (3 launches; g_deg pre-zeroed by aggregate)
    k_degree<<<(N_EDGES + 255) / 256, 256>>>(ei);
    k_alloc<<<NB_SCAN, 256>>>();
    k_bucket<<<(N_EDGES + 255) / 256, 256>>>(ei);

    // join: aggregate needs both branches
    cudaStreamWaitEvent((cudaStream_t)0, ev_join, 0);
    k_aggregate<<<(N_NODES + 7) / 8, 256>>>(att, bias, out);
}